// round 3
// baseline (speedup 1.0000x reference)
#include <cuda_runtime.h>
#include <math.h>

#define HEAD_SIZE   128
#define NUM_Q       32
#define NUM_K       8
#define NUM_QK      (NUM_Q + NUM_K)          // 40 heads get norm+rope
#define ROW_ELEMS   (48 * HEAD_SIZE)         // 6144 floats per token
#define V_OFFSET    (NUM_QK * HEAD_SIZE)     // 5120
#define EPS         1e-6f

__global__ __launch_bounds__(256, 5)
void rope_qknorm_kernel(const float* __restrict__ qkv,
                        const float* __restrict__ q_weight,
                        const float* __restrict__ k_weight,
                        const int*   __restrict__ positions,
                        float* __restrict__ out)
{
    __shared__ float s_cos[64];
    __shared__ float s_sin[64];

    const int t    = blockIdx.x;
    const int tid  = threadIdx.x;
    const int warp = tid >> 5;
    const int lane = tid & 31;

    // ---- per-token cos/sin table (64 rotary freqs) ----
    // Mirror the reference's f32 arithmetic EXACTLY:
    //   inv_freq = 1.0f / powf(10000.0f, (2j)/128.0f)   (XLA f32 pow == __nv_powf)
    //   arg      = (float)pos * inv_freq                (f32 multiply)
    //   cos/sin via libdevice cosf/sinf
    if (tid < 64) {
        float e     = (float)(2 * tid) / 128.0f;
        float inv_f = 1.0f / powf(10000.0f, e);
        float pos_f = (float)positions[t];
        float arg   = pos_f * inv_f;
        s_cos[tid] = cosf(arg);
        s_sin[tid] = sinf(arg);
    }
    __syncthreads();

    const float* __restrict__ row  = qkv + (size_t)t * ROW_ELEMS;
    float*       __restrict__ orow = out + (size_t)t * ROW_ELEMS;

    // ---- per-lane loop invariants (lane owns elems {2l,2l+1} and {2l+64,2l+65}) ----
    const float2 c2  = ((const float2*)s_cos)[lane];
    const float2 sn2 = ((const float2*)s_sin)[lane];
    const float2 wqa = ((const float2*)q_weight)[lane];       // idx 2l, 2l+1
    const float2 wqb = ((const float2*)q_weight)[lane + 32];  // idx 2l+64, 2l+65
    const float2 wka = ((const float2*)k_weight)[lane];
    const float2 wkb = ((const float2*)k_weight)[lane + 32];

    // ---- 40 heads, one warp per head, 5 heads/warp ----
    // heads i*8+warp: i=0..3 are Q heads (0..31), i=4 is K head (32..39)
    #pragma unroll
    for (int i = 0; i < 5; i++) {
        const int h = warp + i * 8;
        const float2* __restrict__ hp = (const float2*)(row  + h * HEAD_SIZE);
        float2*       __restrict__ op = (float2*)      (orow + h * HEAD_SIZE);

        float2 a = hp[lane];        // elems 2l, 2l+1     (first half)
        float2 b = hp[lane + 32];   // elems 2l+64, 2l+65 (second half)

        float ss = a.x * a.x + a.y * a.y + b.x * b.x + b.y * b.y;
        #pragma unroll
        for (int o = 16; o; o >>= 1)
            ss += __shfl_xor_sync(0xffffffffu, ss, o);

        const float inv = rsqrtf(ss * (1.0f / HEAD_SIZE) + EPS);

        const float2 wa = (i < 4) ? wqa : wka;
        const float2 wb = (i < 4) ? wqb : wkb;

        // match reference order: (x * inv) * w
        const float ax = (a.x * inv) * wa.x;
        const float ay = (a.y * inv) * wa.y;
        const float bx = (b.x * inv) * wb.x;
        const float by = (b.y * inv) * wb.y;

        // NeoX rotate: pair (j, j+64), lane-local
        float2 o0, o1;
        o0.x = ax * c2.x - bx * sn2.x;
        o0.y = ay * c2.y - by * sn2.y;
        o1.x = bx * c2.x + ax * sn2.x;
        o1.y = by * c2.y + ay * sn2.y;

        op[lane]      = o0;
        op[lane + 32] = o1;
    }

    // ---- V passthrough: 1024 floats = 256 float4, one per thread ----
    const float4* __restrict__ v4 = (const float4*)(row  + V_OFFSET);
    float4*       __restrict__ o4 = (float4*)(orow + V_OFFSET);
    o4[tid] = v4[tid];
}

extern "C" void kernel_launch(void* const* d_in, const int* in_sizes, int n_in,
                              void* d_out, int out_size)
{
    const float* qkv       = (const float*)d_in[0];
    const float* q_weight  = (const float*)d_in[1];
    const float* k_weight  = (const float*)d_in[2];
    const int*   positions = (const int*)  d_in[3];
    float*       out       = (float*)d_out;

    const int T = in_sizes[3];   // 8192 tokens
    rope_qknorm_kernel<<<T, 256>>>(qkv, q_weight, k_weight, positions, out);
}

// round 4
// speedup vs baseline: 1.0173x; 1.0173x over previous
#include <cuda_runtime.h>
#include <math.h>

#define HEAD_SIZE   128
#define NUM_Q       32
#define NUM_K       8
#define NUM_QK      (NUM_Q + NUM_K)          // 40 heads get norm+rope
#define ROW_ELEMS   (48 * HEAD_SIZE)         // 6144 floats per token
#define V_OFFSET    (NUM_QK * HEAD_SIZE)     // 5120
#define EPS         1e-6f

__global__ __launch_bounds__(256, 4)
void rope_qknorm_kernel(const float* __restrict__ qkv,
                        const float* __restrict__ q_weight,
                        const float* __restrict__ k_weight,
                        const int*   __restrict__ positions,
                        float* __restrict__ out)
{
    __shared__ float s_cos[64];
    __shared__ float s_sin[64];

    const int t    = blockIdx.x;
    const int tid  = threadIdx.x;
    const int warp = tid >> 5;
    const int lane = tid & 31;

    const float* __restrict__ row  = qkv + (size_t)t * ROW_ELEMS;
    float*       __restrict__ orow = out + (size_t)t * ROW_ELEMS;

    // ================= PHASE 1: front-batch ALL global loads =================
    // Lane owns elems {2l,2l+1} (first half) and {2l+64,2l+65} (second half)
    // of each of its 5 heads. 10x LDG.64 + 1x LDG.128, all independent.
    float2 a[5], b[5];
    #pragma unroll
    for (int i = 0; i < 5; i++) {
        const int h = warp + i * 8;      // i=0..3 -> Q heads, i=4 -> K head
        const float2* __restrict__ hp = (const float2*)(row + h * HEAD_SIZE);
        a[i] = hp[lane];
        b[i] = hp[lane + 32];
    }
    const float4 v = ((const float4*)(row + V_OFFSET))[tid];

    // weights (L1/L2-resident after first wave)
    const float2 wqa = __ldg((const float2*)q_weight + lane);
    const float2 wqb = __ldg((const float2*)q_weight + lane + 32);
    const float2 wka = __ldg((const float2*)k_weight + lane);
    const float2 wkb = __ldg((const float2*)k_weight + lane + 32);

    // ============ PHASE 2: sincos table, overlapped with loads ==============
    // Mirror the reference's f32 arithmetic EXACTLY:
    //   inv_freq = 1.0f / powf(10000.0f, (2j)/128.0f); arg = (float)pos * inv_freq
    if (tid < 64) {
        float e     = (float)(2 * tid) / 128.0f;
        float inv_f = 1.0f / powf(10000.0f, e);
        float pos_f = (float)positions[t];
        float arg   = pos_f * inv_f;
        s_cos[tid] = cosf(arg);
        s_sin[tid] = sinf(arg);
    }

    // ============ PHASE 3: per-head RMS (consumes loads, no cos/sin) ========
    float inv[5];
    #pragma unroll
    for (int i = 0; i < 5; i++) {
        float ss = a[i].x * a[i].x + a[i].y * a[i].y
                 + b[i].x * b[i].x + b[i].y * b[i].y;
        #pragma unroll
        for (int o = 16; o; o >>= 1)
            ss += __shfl_xor_sync(0xffffffffu, ss, o);
        inv[i] = rsqrtf(ss * (1.0f / HEAD_SIZE) + EPS);
    }

    __syncthreads();

    // ============ PHASE 4: rotate + store ===================================
    const float2 c2  = ((const float2*)s_cos)[lane];
    const float2 sn2 = ((const float2*)s_sin)[lane];

    #pragma unroll
    for (int i = 0; i < 5; i++) {
        const int h = warp + i * 8;
        float2* __restrict__ op = (float2*)(orow + h * HEAD_SIZE);

        const float2 wa = (i < 4) ? wqa : wka;
        const float2 wb = (i < 4) ? wqb : wkb;

        // match reference order: (x * inv) * w
        const float ax = (a[i].x * inv[i]) * wa.x;
        const float ay = (a[i].y * inv[i]) * wa.y;
        const float bx = (b[i].x * inv[i]) * wb.x;
        const float by = (b[i].y * inv[i]) * wb.y;

        float2 o0, o1;
        o0.x = ax * c2.x - bx * sn2.x;
        o0.y = ay * c2.y - by * sn2.y;
        o1.x = bx * c2.x + ax * sn2.x;
        o1.y = by * c2.y + ay * sn2.y;

        op[lane]      = o0;
        op[lane + 32] = o1;
    }

    // V passthrough
    ((float4*)(orow + V_OFFSET))[tid] = v;
}

extern "C" void kernel_launch(void* const* d_in, const int* in_sizes, int n_in,
                              void* d_out, int out_size)
{
    const float* qkv       = (const float*)d_in[0];
    const float* q_weight  = (const float*)d_in[1];
    const float* k_weight  = (const float*)d_in[2];
    const int*   positions = (const int*)  d_in[3];
    float*       out       = (float*)d_out;

    const int T = in_sizes[3];   // 8192 tokens
    rope_qknorm_kernel<<<T, 256>>>(qkv, q_weight, k_weight, positions, out);
}